// round 6
// baseline (speedup 1.0000x reference)
#include <cuda_runtime.h>

// Shape fixed by dataset: [B=2, 1, D=160, H=192, W=160] fp32.
#define DW 160
#define DH 192
#define DD 160
#define DB 2
#define PS (DH * DW)              // plane stride = 30720 floats

#define CZ   16                   // z-outputs per block
#define NCHUNK (DD / CZ)          // 10
#define TY   8                    // output rows per block
#define TXN  40                   // thread columns (40*4 = 160 = full W)
#define NT   320
#define SMS  168                  // smem row stride in floats (3 pad | halo | 160 | halo | 3 pad)
#define SMROWS 10                 // TY + 2
#define PLANEF (SMROWS * SMS)     // 1680 floats per plane per tensor
#define NS   3                    // cp.async ring stages
#define NBLOCKS ((DH / TY) * DB * NCHUNK)   // 480

__device__ double       g_acc = 0.0;
__device__ unsigned int g_cnt = 0;

__device__ __forceinline__ void cp16(unsigned saddr, const float* gaddr, unsigned sz) {
    asm volatile("cp.async.cg.shared.global [%0], [%1], 16, %2;\n"
                 :: "r"(saddr), "l"(gaddr), "r"(sz));
}
__device__ __forceinline__ void cp_commit() {
    asm volatile("cp.async.commit_group;\n");
}
__device__ __forceinline__ void cp_wait1() {
    asm volatile("cp.async.wait_group 1;\n");
}

__global__ __launch_bounds__(NT, 3) void sobel_loss_kernel(
    const float* __restrict__ moved, const float* __restrict__ label,
    float* __restrict__ out)
{
    __shared__ __align__(16) float smb[NS][2][PLANEF];   // [stage][m/l][plane]
    __shared__ float red[NT / 32];

    const int tid  = threadIdx.x;
    const int txi  = tid % TXN;           // 0..39
    const int tyi  = tid / TXN;           // 0..7
    const int lane = tid & 31;

    const int y0 = blockIdx.y * TY;
    const int b  = blockIdx.z / NCHUNK;
    const int z0 = (blockIdx.z % NCHUNK) * CZ;

    const size_t vol = (size_t)DD * PS;
    const float* mp = moved + (size_t)b * vol;
    const float* lp = label + (size_t)b * vol;

    // ---- cp.async slots (addresses fixed per plane except z offset) ----
    // slot 0: row r0 = tyi (rows 0..7 of the 10-row halo window)
    const int  gy0  = y0 - 1 + tyi;
    const bool yv0  = (gy0 >= 0) && (gy0 < DH);
    const int  gy0c = gy0 < 0 ? 0 : (gy0 >= DH ? DH - 1 : gy0);
    const int  goff0 = gy0c * DW + 4 * txi;
    const unsigned so0 = (unsigned)((tyi * SMS + 4 + 4 * txi) * 4);   // bytes
    // slot 1: rows 8,9 handled by tid < 80
    const bool kv1  = tid < (SMROWS * TXN - NT);   // tid < 80
    const int  k1   = tid + NT;
    const int  r1   = k1 / TXN;
    const int  c1   = k1 % TXN;
    const int  gy1  = y0 - 1 + r1;
    const bool yv1  = (gy1 >= 0) && (gy1 < DH);
    const int  gy1c = gy1 < 0 ? 0 : (gy1 >= DH ? DH - 1 : gy1);
    const int  goff1 = gy1c * DW + 4 * c1;
    const unsigned so1 = (unsigned)((r1 * SMS + 4 + 4 * c1) * 4);

    const unsigned smbase = (unsigned)__cvta_generic_to_shared(&smb[0][0][0]);

    // zero the x-halo columns (cols 3 and 164) of all stages/tensors, once
    if (tid < NS * 2 * SMROWS * 2) {            // 120
        int side = tid & 1;
        int rest = tid >> 1;
        int rr = rest % SMROWS;
        int tt = (rest / SMROWS) & 1;
        int st = rest / (SMROWS * 2);
        smb[st][tt][rr * SMS + (side ? 4 + DW : 3)] = 0.0f;
    }

    // ---- issue one plane's loads into stage 'st' ----
    auto issue = [&](int p, int st) {   // p: plane index 0..CZ+1 (z = z0-1+p)
        const int z  = z0 - 1 + p;
        const bool zin = (z >= 0) && (z < DD);
        const int zc = z < 0 ? 0 : (z >= DD ? DD - 1 : z);
        const size_t zb = (size_t)zc * PS;
        const unsigned szm0 = (zin && yv0) ? 16u : 0u;
        const unsigned sam = smbase + (unsigned)((st * 2 + 0) * PLANEF * 4);
        const unsigned sal = smbase + (unsigned)((st * 2 + 1) * PLANEF * 4);
        cp16(sam + so0, mp + zb + goff0, szm0);
        cp16(sal + so0, lp + zb + goff0, szm0);
        if (kv1) {
            const unsigned szm1 = (zin && yv1) ? 16u : 0u;
            cp16(sam + so1, mp + zb + goff1, szm1);
            cp16(sal + so1, lp + zb + goff1, szm1);
        }
    };

    const bool fbL = (lane == 0)  || (txi == 0);
    const bool fbR = (lane == 31) || (txi == TXN - 1);

    float acc = 0.0f;

    // state: P completes this plane, Q completes next plane (roles swap each step)
    float Agx[4], Agy[4], Agz[4], Bgx[4], Bgy[4], Bgz[4];
    #pragma unroll
    for (int j = 0; j < 4; ++j) {
        Agx[j] = Agy[j] = Agz[j] = 0.f;
        Bgx[j] = Bgy[j] = Bgz[j] = 0.f;
    }

    // per-plane partials + accumulator update
    auto plane_step = [&](int cs, float* Pgx, float* Pgy, float* Pgz,
                          float* Qgx, float* Qgy, float* Qgz, bool emit) {
        const float* mb = &smb[cs][0][tyi * SMS + 4 * txi];
        const float* lb = &smb[cs][1][tyi * SMS + 4 * txi];
        float X[4], Y[4], S[4];
        float sr[3][4], dr[3][4];
        #pragma unroll
        for (int rr = 0; rr < 3; ++rr) {
            const float* mr = mb + rr * SMS;
            const float* lr = lb + rr * SMS;
            float4 m4 = *(const float4*)(mr + 4);
            float4 l4 = *(const float4*)(lr + 4);
            float d1 = m4.x - l4.x, d2 = m4.y - l4.y;
            float d3 = m4.z - l4.z, d4 = m4.w - l4.w;
            float dl = __shfl_up_sync(0xffffffffu, d4, 1);
            float dR = __shfl_down_sync(0xffffffffu, d1, 1);
            if (fbL) dl = mr[3] - lr[3];     // zero-padded halo cols for x-edges
            if (fbR) dR = mr[8] - lr[8];
            sr[rr][0] = dl + 2.f * d1 + d2;  dr[rr][0] = d2 - dl;
            sr[rr][1] = d1 + 2.f * d2 + d3;  dr[rr][1] = d3 - d1;
            sr[rr][2] = d2 + 2.f * d3 + d4;  dr[rr][2] = d4 - d2;
            sr[rr][3] = d3 + 2.f * d4 + dR;  dr[rr][3] = dR - d3;
        }
        #pragma unroll
        for (int j = 0; j < 4; ++j) {
            X[j] = dr[0][j] + 2.f * dr[1][j] + dr[2][j];
            S[j] = sr[0][j] + 2.f * sr[1][j] + sr[2][j];
            Y[j] = sr[2][j] - sr[0][j];
        }
        #pragma unroll
        for (int j = 0; j < 4; ++j) {
            if (emit)
                acc += fabsf(Pgx[j] + X[j]) + fabsf(Pgy[j] + Y[j]) + fabsf(Pgz[j] + S[j]);
            Qgx[j] += 2.f * X[j];
            Qgy[j] += 2.f * Y[j];
            Pgx[j] = X[j]; Pgy[j] = Y[j]; Pgz[j] = -S[j];   // new output slot
        }
    };

    // ---- prologue: stages 0,1 = planes 0,1 ----
    issue(0, 0); cp_commit();
    issue(1, 1); cp_commit();

    // t = 0
    cp_wait1(); __syncthreads();
    issue(2, 2); cp_commit();
    plane_step(0, Agx, Agy, Agz, Bgx, Bgy, Bgz, false);
    // t = 1
    cp_wait1(); __syncthreads();
    issue(3, 0); cp_commit();
    plane_step(1, Bgx, Bgy, Bgz, Agx, Agy, Agz, false);

    // t = 2 .. CZ+1 (emit), plane to issue starts at 4
    int ip = 4;          // next plane to issue
    int is = 1;          // its stage
    int cs = 2;          // stage to compute
    #pragma unroll 2
    for (int t = 2; t < CZ + 2; t += 2) {
        cp_wait1(); __syncthreads();
        if (ip <= CZ + 1) issue(ip, is);
        cp_commit(); ++ip; is = (is == NS - 1) ? 0 : is + 1;
        plane_step(cs, Agx, Agy, Agz, Bgx, Bgy, Bgz, true);
        cs = (cs == NS - 1) ? 0 : cs + 1;

        cp_wait1(); __syncthreads();
        if (ip <= CZ + 1) issue(ip, is);
        cp_commit(); ++ip; is = (is == NS - 1) ? 0 : is + 1;
        plane_step(cs, Bgx, Bgy, Bgz, Agx, Agy, Agz, true);
        cs = (cs == NS - 1) ? 0 : cs + 1;
    }

    // ---- reduction ----
    #pragma unroll
    for (int o = 16; o > 0; o >>= 1)
        acc += __shfl_down_sync(0xffffffffu, acc, o);
    if (lane == 0) red[tid >> 5] = acc;
    __syncthreads();

    if (tid == 0) {
        float s = 0.0f;
        #pragma unroll
        for (int i = 0; i < NT / 32; ++i) s += red[i];
        atomicAdd(&g_acc, (double)s);
        __threadfence();
        unsigned old = atomicInc(&g_cnt, NBLOCKS - 1);
        if (old == NBLOCKS - 1) {
            double total = atomicAdd(&g_acc, 0.0);
            out[0] = (float)(total / (3.0 * (double)DB * DD * DH * DW));
            g_acc = 0.0;
            __threadfence();
        }
    }
}

extern "C" void kernel_launch(void* const* d_in, const int* in_sizes, int n_in,
                              void* d_out, int out_size)
{
    (void)in_sizes; (void)n_in; (void)out_size;
    const float* moved = (const float*)d_in[0];
    const float* label = (const float*)d_in[1];
    float* out = (float*)d_out;

    dim3 grid(1, DH / TY, DB * NCHUNK);   // (1, 24, 20) = 480 blocks
    sobel_loss_kernel<<<grid, NT>>>(moved, label, out);
}